// round 4
// baseline (speedup 1.0000x reference)
#include <cuda_runtime.h>
#include <cstdint>

// FastSeqProp: instance-norm(L=200) -> scale/shift -> softmax over C=4
// -> exact JAX threefry categorical (key 42, partitionable) -> straight-through
// -> pad to (N,4,600); outputs [softmax_padded, sampled_padded].
//
// Compute-path float math is bit-identical to the validated R2/R3 kernels
// (zero argmax flips). R4 changes data movement only:
//  - soft/samp staged in smem, cooperative float4 copy-out of both outputs
//  - up/down pads loaded once as float4, stored twice (no register staging)
//  - 25th warp-draw of threefry moved to the otherwise-idle warp 7
//  - __launch_bounds__(256,7) for 56/64 warps per SM

#define LEN   200
#define LPAD  600
#define NCH   4
#define EPSV  1e-5f
#define TINYF 1.17549435e-38f

__device__ __forceinline__ uint32_t rotl32(uint32_t x, int r) {
    return (x << r) | (x >> (32 - r));
}

__device__ __forceinline__ void tf_round(uint32_t& x0, uint32_t& x1, int r) {
    x0 += x1;
    x1 = rotl32(x1, r);
    x1 ^= x0;
}

__device__ __forceinline__ uint32_t tf_bits_k42(uint32_t idx) {
    // threefry2x32, key=(0,42), counter=(0, idx); out = x0 ^ x1 (partitionable)
    const uint32_t ks0 = 0u;
    const uint32_t ks1 = 42u;
    const uint32_t ks2 = 0x1BD11BDAu ^ ks0 ^ ks1;
    uint32_t x0 = 0u + ks0;
    uint32_t x1 = idx + ks1;

    tf_round(x0, x1, 13); tf_round(x0, x1, 15); tf_round(x0, x1, 26); tf_round(x0, x1, 6);
    x0 += ks1; x1 += ks2 + 1u;
    tf_round(x0, x1, 17); tf_round(x0, x1, 29); tf_round(x0, x1, 16); tf_round(x0, x1, 24);
    x0 += ks2; x1 += ks0 + 2u;
    tf_round(x0, x1, 13); tf_round(x0, x1, 15); tf_round(x0, x1, 26); tf_round(x0, x1, 6);
    x0 += ks0; x1 += ks1 + 3u;
    tf_round(x0, x1, 17); tf_round(x0, x1, 29); tf_round(x0, x1, 16); tf_round(x0, x1, 24);
    x0 += ks1; x1 += ks2 + 4u;
    tf_round(x0, x1, 13); tf_round(x0, x1, 15); tf_round(x0, x1, 26); tf_round(x0, x1, 6);
    x0 += ks2; x1 += ks0 + 5u;

    return x0 ^ x1;
}

__device__ __forceinline__ float gumbel_from_bits(uint32_t bits) {
    float f = __uint_as_float((bits >> 9) | 0x3f800000u) - 1.0f;
    float u = fmaxf(f, TINYF);
    return -logf(-logf(u));   // accurate logf: matches XLA/libdevice bit-for-bit
}

__global__ __launch_bounds__(256, 7) void fastseqprop_kernel(
    const float* __restrict__ ts,    // (N,4,200)
    const float* __restrict__ scw,   // (N,4,1)
    const float* __restrict__ shw,   // (N,4,1)
    const float* __restrict__ up,    // (N,4,200)
    const float* __restrict__ dn,    // (N,4,200)
    float* __restrict__ out,         // (2,N,4,600) flattened
    uint32_t half_out)               // N*4*600
{
    const uint32_t n    = blockIdx.x;
    const uint32_t t    = threadIdx.x;
    const uint32_t lane = t & 31u;
    const uint32_t wid  = t >> 5;
    const bool act = (t < LEN);

    __shared__ float  red[8][4];
    __shared__ float  bc[4];
    __shared__ float  sgum[NCH * LEN];     // gumbel values, layout [c*200 + l]
    __shared__ float4 smid4[2][NCH * 50];  // [0]=softmax, [1]=sampled, f4 layout

    const uint32_t in_base = n * (NCH * LEN);
    const uint32_t wbase   = n * NCH;

    // ---- preload normalization inputs + weights (hidden under threefry) ----
    float x0 = 0.f, x1 = 0.f, x2 = 0.f, x3 = 0.f;
    float scv[4], shv[4];
    if (act) {
        x0 = ts[in_base + 0 * LEN + t];
        x1 = ts[in_base + 1 * LEN + t];
        x2 = ts[in_base + 2 * LEN + t];
        x3 = ts[in_base + 3 * LEN + t];
        #pragma unroll
        for (int c = 0; c < 4; c++) {
            scv[c] = scw[wbase + (uint32_t)c];
            shv[c] = shw[wbase + (uint32_t)c];
        }
    }

    // ---- dense threefry: 800 draws; 3 per thread, 4th on idle warp 7 ----
    // flat gumbel index for (n,l,c) in shape (N,L,4): gbase + (l*4 + c)
    {
        const uint32_t gbase = n * (LEN * NCH);
        const uint32_t j0 = t;
        const uint32_t j1 = t + 256u;
        const uint32_t j2 = t + 512u;
        const uint32_t b0 = tf_bits_k42(gbase + j0);
        const uint32_t b1 = tf_bits_k42(gbase + j1);
        const uint32_t b2 = tf_bits_k42(gbase + j2);
        sgum[(j0 & 3u) * LEN + (j0 >> 2)] = gumbel_from_bits(b0);
        sgum[(j1 & 3u) * LEN + (j1 >> 2)] = gumbel_from_bits(b1);
        sgum[(j2 & 3u) * LEN + (j2 >> 2)] = gumbel_from_bits(b2);
        if (t >= 224u) {
            const uint32_t j3 = (t - 224u) + 768u;
            const uint32_t b3 = tf_bits_k42(gbase + j3);
            sgum[(j3 & 3u) * LEN + (j3 >> 2)] = gumbel_from_bits(b3);
        }
    }

    // ---- pass 1: sums -> means (bit-identical tree to R2/R3) ----
    {
        float v0 = x0, v1 = x1, v2 = x2, v3 = x3;
        #pragma unroll
        for (int o = 16; o > 0; o >>= 1) {
            v0 += __shfl_down_sync(0xffffffffu, v0, o);
            v1 += __shfl_down_sync(0xffffffffu, v1, o);
            v2 += __shfl_down_sync(0xffffffffu, v2, o);
            v3 += __shfl_down_sync(0xffffffffu, v3, o);
        }
        if (lane == 0) { red[wid][0] = v0; red[wid][1] = v1; red[wid][2] = v2; red[wid][3] = v3; }
        __syncthreads();
        if (t == 0) {
            float s0 = 0.f, s1 = 0.f, s2 = 0.f, s3 = 0.f;
            #pragma unroll
            for (int w = 0; w < 8; w++) { s0 += red[w][0]; s1 += red[w][1]; s2 += red[w][2]; s3 += red[w][3]; }
            bc[0] = s0; bc[1] = s1; bc[2] = s2; bc[3] = s3;
        }
        __syncthreads();
    }
    const float m0 = bc[0] / 200.0f;
    const float m1 = bc[1] / 200.0f;
    const float m2 = bc[2] / 200.0f;
    const float m3 = bc[3] / 200.0f;

    const float d0 = act ? (x0 - m0) : 0.f;
    const float d1 = act ? (x1 - m1) : 0.f;
    const float d2 = act ? (x2 - m2) : 0.f;
    const float d3 = act ? (x3 - m3) : 0.f;

    // ---- pass 2: centered sum of squares -> biased variance ----
    {
        float v0 = d0 * d0, v1 = d1 * d1, v2 = d2 * d2, v3 = d3 * d3;
        #pragma unroll
        for (int o = 16; o > 0; o >>= 1) {
            v0 += __shfl_down_sync(0xffffffffu, v0, o);
            v1 += __shfl_down_sync(0xffffffffu, v1, o);
            v2 += __shfl_down_sync(0xffffffffu, v2, o);
            v3 += __shfl_down_sync(0xffffffffu, v3, o);
        }
        if (lane == 0) { red[wid][0] = v0; red[wid][1] = v1; red[wid][2] = v2; red[wid][3] = v3; }
        __syncthreads();
        if (t == 0) {
            float s0 = 0.f, s1 = 0.f, s2 = 0.f, s3 = 0.f;
            #pragma unroll
            for (int w = 0; w < 8; w++) { s0 += red[w][0]; s1 += red[w][1]; s2 += red[w][2]; s3 += red[w][3]; }
            bc[0] = s0; bc[1] = s1; bc[2] = s2; bc[3] = s3;
        }
        __syncthreads();
    }

    // ---- per-position compute (t < 200): softmax + sample -> smem ----
    if (act) {
        const float var0 = bc[0] / 200.0f;
        const float var1 = bc[1] / 200.0f;
        const float var2 = bc[2] / 200.0f;
        const float var3 = bc[3] / 200.0f;

        const float r0 = rsqrtf(var0 + EPSV);
        const float r1 = rsqrtf(var1 + EPSV);
        const float r2 = rsqrtf(var2 + EPSV);
        const float r3 = rsqrtf(var3 + EPSV);

        float sc[4];
        sc[0] = (d0 * r0) * scv[0] + shv[0];
        sc[1] = (d1 * r1) * scv[1] + shv[1];
        sc[2] = (d2 * r2) * scv[2] + shv[2];
        sc[3] = (d3 * r3) * scv[3] + shv[3];

        const float mx  = fmaxf(fmaxf(sc[0], sc[1]), fmaxf(sc[2], sc[3]));
        float sh[4], ex[4];
        #pragma unroll
        for (int c = 0; c < 4; c++) { sh[c] = sc[c] - mx; ex[c] = expf(sh[c]); }
        const float ssum = ((ex[0] + ex[1]) + ex[2]) + ex[3];
        float soft[4];
        #pragma unroll
        for (int c = 0; c < 4; c++) soft[c] = ex[c] / ssum;
        const float lse = logf(ssum);

        // argmax over gumbel + log_softmax (first max wins)
        float best = -1e30f;
        int   besti = 0;
        #pragma unroll
        for (int c = 0; c < 4; c++) {
            const float g = sgum[(uint32_t)c * LEN + t];
            const float v = g + (sh[c] - lse);
            if (v > best) { best = v; besti = c; }
        }

        float* ssoft = (float*)&smid4[0][0];
        float* ssamp = (float*)&smid4[1][0];
        #pragma unroll
        for (int c = 0; c < 4; c++) {
            const float s_v = soft[c];
            const float oh  = (c == besti) ? 1.0f : 0.0f;
            ssoft[(uint32_t)c * LEN + t] = s_v;
            ssamp[(uint32_t)c * LEN + t] = (oh - s_v) + s_v;  // straight-through
        }
    }
    __syncthreads();

    // ---- cooperative float4 copy-out of both outputs ----
    // Each output channel row: [ up(200) | mid(200) | dn(200) ] = 150 float4.
    const float4* up4 = (const float4*)up + n * 200u;
    const float4* dn4 = (const float4*)dn + n * 200u;
    float4* o0 = (float4*)out + n * 600u;
    float4* o1 = (float4*)out + (half_out >> 2) + n * 600u;

    #pragma unroll
    for (uint32_t u = t; u < 600u; u += 256u) {
        const uint32_t c = u / 150u;
        const uint32_t q = u - c * 150u;
        float4 v0, v1;
        if (q < 50u) {
            const float4 p = up4[c * 50u + q];
            v0 = p; v1 = p;
        } else if (q < 100u) {
            v0 = smid4[0][c * 50u + (q - 50u)];
            v1 = smid4[1][c * 50u + (q - 50u)];
        } else {
            const float4 p = dn4[c * 50u + (q - 100u)];
            v0 = p; v1 = p;
        }
        o0[c * 150u + q] = v0;
        o1[c * 150u + q] = v1;
    }
}

extern "C" void kernel_launch(void* const* d_in, const int* in_sizes, int n_in,
                              void* d_out, int out_size) {
    const float* ts  = (const float*)d_in[0];
    const float* scw = (const float*)d_in[1];
    const float* shw = (const float*)d_in[2];
    const float* up  = (const float*)d_in[3];
    const float* dn  = (const float*)d_in[4];
    float* out = (float*)d_out;

    const int nseq = in_sizes[0] / (NCH * LEN);          // 8192
    const uint32_t half_out = (uint32_t)(out_size / 2);  // N*4*600

    fastseqprop_kernel<<<nseq, 256>>>(ts, scw, shw, up, dn, out, half_out);
}

// round 5
// speedup vs baseline: 1.2008x; 1.2008x over previous
#include <cuda_runtime.h>
#include <cstdint>

// FastSeqProp: instance-norm(L=200) -> scale/shift -> softmax over C=4
// -> exact JAX threefry categorical (key 42, partitionable) -> straight-through
// -> pad to (N,4,600); outputs [softmax_padded, sampled_padded].
//
// R5: exponential-races argmin (drops outer logf + lse), __fdividef softmax,
// uniform divides/rsqrt hoisted to thread 0. Threefry bits and inner
// -log(u) remain bit-exact; reduction tree unchanged from validated kernels.

#define LEN   200
#define LPAD  600
#define NCH   4
#define EPSV  1e-5f
#define TINYF 1.17549435e-38f

__device__ __forceinline__ uint32_t rotl32(uint32_t x, int r) {
    return (x << r) | (x >> (32 - r));
}

__device__ __forceinline__ void tf_round(uint32_t& x0, uint32_t& x1, int r) {
    x0 += x1;
    x1 = rotl32(x1, r);
    x1 ^= x0;
}

__device__ __forceinline__ uint32_t tf_bits_k42(uint32_t idx) {
    // threefry2x32, key=(0,42), counter=(0, idx); out = x0 ^ x1 (partitionable)
    const uint32_t ks0 = 0u;
    const uint32_t ks1 = 42u;
    const uint32_t ks2 = 0x1BD11BDAu ^ ks0 ^ ks1;
    uint32_t x0 = 0u + ks0;
    uint32_t x1 = idx + ks1;

    tf_round(x0, x1, 13); tf_round(x0, x1, 15); tf_round(x0, x1, 26); tf_round(x0, x1, 6);
    x0 += ks1; x1 += ks2 + 1u;
    tf_round(x0, x1, 17); tf_round(x0, x1, 29); tf_round(x0, x1, 16); tf_round(x0, x1, 24);
    x0 += ks2; x1 += ks0 + 2u;
    tf_round(x0, x1, 13); tf_round(x0, x1, 15); tf_round(x0, x1, 26); tf_round(x0, x1, 6);
    x0 += ks0; x1 += ks1 + 3u;
    tf_round(x0, x1, 17); tf_round(x0, x1, 29); tf_round(x0, x1, 16); tf_round(x0, x1, 24);
    x0 += ks1; x1 += ks2 + 4u;
    tf_round(x0, x1, 13); tf_round(x0, x1, 15); tf_round(x0, x1, 26); tf_round(x0, x1, 6);
    x0 += ks2; x1 += ks0 + 5u;

    return x0 ^ x1;
}

// w = -log(u), u = uniform in [tiny,1) from bits; exact logf (matches XLA).
__device__ __forceinline__ float expw_from_bits(uint32_t bits) {
    float f = __uint_as_float((bits >> 9) | 0x3f800000u) - 1.0f;
    float u = fmaxf(f, TINYF);
    return 0.0f - logf(u);
}

__global__ __launch_bounds__(256) void fastseqprop_kernel(
    const float* __restrict__ ts,    // (N,4,200)
    const float* __restrict__ scw,   // (N,4,1)
    const float* __restrict__ shw,   // (N,4,1)
    const float* __restrict__ up,    // (N,4,200)
    const float* __restrict__ dn,    // (N,4,200)
    float* __restrict__ out,         // (2,N,4,600) flattened
    uint32_t half_out)               // N*4*600
{
    const uint32_t n    = blockIdx.x;
    const uint32_t t    = threadIdx.x;
    const uint32_t lane = t & 31u;
    const uint32_t wid  = t >> 5;
    const bool act = (t < LEN);

    __shared__ float red[8][4];
    __shared__ float bcm[4];            // means
    __shared__ float bcr[4];            // rsqrt(var+eps)
    __shared__ float sw[NCH * LEN];     // w = -log(u), layout [c*200 + l]

    const uint32_t base = n * (NCH * LEN);   // == flat gumbel base (N,L,4)
    const uint32_t wbase = n * NCH;

    // ---- preload normalization inputs + weights (hidden under threefry) ----
    float x0 = 0.f, x1 = 0.f, x2 = 0.f, x3 = 0.f;
    float scv[4], shv[4];
    if (act) {
        x0 = ts[base + 0 * LEN + t];
        x1 = ts[base + 1 * LEN + t];
        x2 = ts[base + 2 * LEN + t];
        x3 = ts[base + 3 * LEN + t];
        #pragma unroll
        for (int c = 0; c < 4; c++) {
            scv[c] = scw[wbase + (uint32_t)c];
            shv[c] = shw[wbase + (uint32_t)c];
        }
    }

    // ---- dense threefry: 800 draws; 3 per thread, 4th on idle warp 7 ----
    {
        const uint32_t j0 = t;
        const uint32_t j1 = t + 256u;
        const uint32_t j2 = t + 512u;
        const uint32_t b0 = tf_bits_k42(base + j0);
        const uint32_t b1 = tf_bits_k42(base + j1);
        const uint32_t b2 = tf_bits_k42(base + j2);
        sw[(j0 & 3u) * LEN + (j0 >> 2)] = expw_from_bits(b0);
        sw[(j1 & 3u) * LEN + (j1 >> 2)] = expw_from_bits(b1);
        sw[(j2 & 3u) * LEN + (j2 >> 2)] = expw_from_bits(b2);
        if (t >= 224u) {
            const uint32_t j3 = (t - 224u) + 768u;
            const uint32_t b3 = tf_bits_k42(base + j3);
            sw[(j3 & 3u) * LEN + (j3 >> 2)] = expw_from_bits(b3);
        }
    }

    // ---- pass 1: sums -> means (bit-identical tree; /200 hoisted to t0) ----
    {
        float v0 = x0, v1 = x1, v2 = x2, v3 = x3;
        #pragma unroll
        for (int o = 16; o > 0; o >>= 1) {
            v0 += __shfl_down_sync(0xffffffffu, v0, o);
            v1 += __shfl_down_sync(0xffffffffu, v1, o);
            v2 += __shfl_down_sync(0xffffffffu, v2, o);
            v3 += __shfl_down_sync(0xffffffffu, v3, o);
        }
        if (lane == 0) { red[wid][0] = v0; red[wid][1] = v1; red[wid][2] = v2; red[wid][3] = v3; }
        __syncthreads();
        if (t == 0) {
            float s0 = 0.f, s1 = 0.f, s2 = 0.f, s3 = 0.f;
            #pragma unroll
            for (int w = 0; w < 8; w++) { s0 += red[w][0]; s1 += red[w][1]; s2 += red[w][2]; s3 += red[w][3]; }
            bcm[0] = s0 / 200.0f; bcm[1] = s1 / 200.0f;
            bcm[2] = s2 / 200.0f; bcm[3] = s3 / 200.0f;
        }
        __syncthreads();
    }
    const float m0 = bcm[0];
    const float m1 = bcm[1];
    const float m2 = bcm[2];
    const float m3 = bcm[3];

    const float d0 = act ? (x0 - m0) : 0.f;
    const float d1 = act ? (x1 - m1) : 0.f;
    const float d2 = act ? (x2 - m2) : 0.f;
    const float d3 = act ? (x3 - m3) : 0.f;

    // ---- pass 2: centered sum of squares -> rsqrt(var+eps) (hoisted) ----
    {
        float v0 = d0 * d0, v1 = d1 * d1, v2 = d2 * d2, v3 = d3 * d3;
        #pragma unroll
        for (int o = 16; o > 0; o >>= 1) {
            v0 += __shfl_down_sync(0xffffffffu, v0, o);
            v1 += __shfl_down_sync(0xffffffffu, v1, o);
            v2 += __shfl_down_sync(0xffffffffu, v2, o);
            v3 += __shfl_down_sync(0xffffffffu, v3, o);
        }
        if (lane == 0) { red[wid][0] = v0; red[wid][1] = v1; red[wid][2] = v2; red[wid][3] = v3; }
        __syncthreads();
        if (t == 0) {
            float s0 = 0.f, s1 = 0.f, s2 = 0.f, s3 = 0.f;
            #pragma unroll
            for (int w = 0; w < 8; w++) { s0 += red[w][0]; s1 += red[w][1]; s2 += red[w][2]; s3 += red[w][3]; }
            bcr[0] = rsqrtf(s0 / 200.0f + EPSV);
            bcr[1] = rsqrtf(s1 / 200.0f + EPSV);
            bcr[2] = rsqrtf(s2 / 200.0f + EPSV);
            bcr[3] = rsqrtf(s3 / 200.0f + EPSV);
        }
        __syncthreads();
    }

    if (!act) return;

    float sc[4];
    sc[0] = (d0 * bcr[0]) * scv[0] + shv[0];
    sc[1] = (d1 * bcr[1]) * scv[1] + shv[1];
    sc[2] = (d2 * bcr[2]) * scv[2] + shv[2];
    sc[3] = (d3 * bcr[3]) * scv[3] + shv[3];

    // softmax over channels; exact expf (feeds argmin), fast divide for probs
    const float mx  = fmaxf(fmaxf(sc[0], sc[1]), fmaxf(sc[2], sc[3]));
    float ex[4];
    #pragma unroll
    for (int c = 0; c < 4; c++) ex[c] = expf(sc[c] - mx);
    const float ssum = ((ex[0] + ex[1]) + ex[2]) + ex[3];
    float soft[4];
    #pragma unroll
    for (int c = 0; c < 4; c++) soft[c] = __fdividef(ex[c], ssum);

    // ---- exponential-races argmin: argmin_c w_c / ex_c (cross-multiplied) ----
    // == argmax_c gumbel_c + log_softmax_c ; first winner kept on ties.
    float wb = sw[t];
    float eb = ex[0];
    int   bi = 0;
    #pragma unroll
    for (int c = 1; c < 4; c++) {
        const float wc = sw[(uint32_t)c * LEN + t];
        if (wc * eb < wb * ex[c]) { wb = wc; eb = ex[c]; bi = c; }
    }

    // ---- write outputs (direct scalar stores, R3 scheme) ----
    float* out0 = out;
    float* out1 = out + half_out;
    const uint32_t obase = n * (NCH * LPAD);

    #pragma unroll
    for (int c = 0; c < 4; c++) {
        const float u_v = up[base + (uint32_t)c * LEN + t];
        const float d_v = dn[base + (uint32_t)c * LEN + t];
        const float s_v = soft[c];
        const float oh  = (c == bi) ? 1.0f : 0.0f;
        const float samp = (oh - s_v) + s_v;   // straight-through

        const uint32_t row = obase + (uint32_t)c * LPAD;
        out0[row + t]           = u_v;
        out0[row + LEN + t]     = s_v;
        out0[row + 2 * LEN + t] = d_v;
        out1[row + t]           = u_v;
        out1[row + LEN + t]     = samp;
        out1[row + 2 * LEN + t] = d_v;
    }
}

extern "C" void kernel_launch(void* const* d_in, const int* in_sizes, int n_in,
                              void* d_out, int out_size) {
    const float* ts  = (const float*)d_in[0];
    const float* scw = (const float*)d_in[1];
    const float* shw = (const float*)d_in[2];
    const float* up  = (const float*)d_in[3];
    const float* dn  = (const float*)d_in[4];
    float* out = (float*)d_out;

    const int nseq = in_sizes[0] / (NCH * LEN);          // 8192
    const uint32_t half_out = (uint32_t)(out_size / 2);  // N*4*600

    fastseqprop_kernel<<<nseq, 256>>>(ts, scw, shw, up, dn, out, half_out);
}